// round 4
// baseline (speedup 1.0000x reference)
#include <cuda_runtime.h>
#include <cuda_bf16.h>
#include <cstdint>
#include <math.h>

#define B_ 4096
#define M_ 306
#define N_ 984
#define LAMBDA_ 0.1f
#define ITERS_ 50
#define NSQ_ 12

#define NP 2048           // padded interleaved (re,im) storage width
#define NI 1968           // 2*N_ live columns
#define BM 128
#define BN 64
#define BK 64             // bf16 elems per K-chunk (128 bytes per row)
#define KC 31             // chunks: 31*64 = 1984 >= NI
#define NT 31             // n tiles: 31*64 = 1984 >= NI

#define ROWB 144          // smem row stride: 128B data + 16B pad (conflict-free ldsm)
#define ATILE (128 * ROWB)            // 18432
#define BTILE (64 * ROWB)             // 9216
#define STAGEB (2 * ATILE + 2 * BTILE)  // Ah, Al, Bh, Bl = 55296
#define SMEM_DYN (3 * STAGEB)           // 165888

// ---------------- static device scratch (no allocations) ----------------
__device__ __nv_bfloat16 g_whi[2][(size_t)B_ * NP];
__device__ __nv_bfloat16 g_wlo[2][(size_t)B_ * NP];
__device__ __nv_bfloat16 g_Bhi[(size_t)NP * NP];   // B^T: row = out col j, col = k
__device__ __nv_bfloat16 g_Blo[(size_t)NP * NP];
__device__ float  g_chat[(size_t)B_ * NP];
__device__ float2 g_Ahat[(size_t)N_ * N_];
__device__ float2 g_G[2][M_ * M_];
__device__ float  g_logacc, g_inv_s, g_step, g_thresh;

// ---------------- PTX helpers ----------------
__device__ __forceinline__ uint32_t smem_u32(const void* p) {
    uint32_t a;
    asm("{ .reg .u64 t; cvta.to.shared.u64 t, %1; cvt.u32.u64 %0, t; }" : "=r"(a) : "l"(p));
    return a;
}
__device__ __forceinline__ void cp16(uint32_t s, const void* g) {
    asm volatile("cp.async.cg.shared.global [%0], [%1], 16;" :: "r"(s), "l"(g));
}
__device__ __forceinline__ void ldsm4(uint32_t* r, uint32_t a) {
    asm volatile("ldmatrix.sync.aligned.m8n8.x4.shared.b16 {%0,%1,%2,%3}, [%4];"
                 : "=r"(r[0]), "=r"(r[1]), "=r"(r[2]), "=r"(r[3]) : "r"(a));
}
__device__ __forceinline__ void mma16816(float* c, const uint32_t* a, uint32_t b0, uint32_t b1) {
    asm volatile(
        "mma.sync.aligned.m16n8k16.row.col.f32.bf16.bf16.f32 "
        "{%0,%1,%2,%3}, {%4,%5,%6,%7}, {%8,%9}, {%0,%1,%2,%3};"
        : "+f"(c[0]), "+f"(c[1]), "+f"(c[2]), "+f"(c[3])
        : "r"(a[0]), "r"(a[1]), "r"(a[2]), "r"(a[3]), "r"(b0), "r"(b1));
}

// ---------------- setup: zero W buffer 0 + logacc ----------------
__global__ void k_zero2() {
    size_t i = (size_t)blockIdx.x * blockDim.x + threadIdx.x;
    size_t n16 = (size_t)B_ * NP * 2 / 16;
    if (i < n16) {
        reinterpret_cast<uint4*>(g_whi[0])[i] = make_uint4(0, 0, 0, 0);
        reinterpret_cast<uint4*>(g_wlo[0])[i] = make_uint4(0, 0, 0, 0);
    }
    if (i == 0) g_logacc = 0.f;
}

// ---------------- spectral norm via Gram + trace-normalized squaring ----
__global__ void k_computeG(const float* __restrict__ pr, const float* __restrict__ pi) {
    __shared__ float2 sA[16][17];
    __shared__ float2 sB[16][17];
    int i0 = blockIdx.y * 16, j0 = blockIdx.x * 16;
    int tx = threadIdx.x, ty = threadIdx.y;
    float cr = 0.f, ci = 0.f;
    for (int n0 = 0; n0 < N_; n0 += 16) {
        int ac = n0 + tx, ar = i0 + ty, br = j0 + ty;
        sA[ty][tx] = (ar < M_ && ac < N_) ? make_float2(pr[ar * N_ + ac], pi[ar * N_ + ac]) : make_float2(0.f, 0.f);
        sB[ty][tx] = (br < M_ && ac < N_) ? make_float2(pr[br * N_ + ac], pi[br * N_ + ac]) : make_float2(0.f, 0.f);
        __syncthreads();
#pragma unroll
        for (int t = 0; t < 16; t++) {
            float2 a = sA[ty][t], b = sB[tx][t];
            cr += a.x * b.x + a.y * b.y;
            ci += a.y * b.x - a.x * b.y;
        }
        __syncthreads();
    }
    int i = i0 + ty, j = j0 + tx;
    if (i < M_ && j < M_) g_G[0][i * M_ + j] = make_float2(cr, ci);
}

__global__ void k_trace(int src, float weight) {
    __shared__ float red[512];
    int t = threadIdx.x;
    red[t] = (t < M_) ? g_G[src][t * (M_ + 1)].x : 0.f;
    __syncthreads();
    for (int s = 256; s > 0; s >>= 1) {
        if (t < s) red[t] += red[t + s];
        __syncthreads();
    }
    if (t == 0) {
        float s = red[0];
        g_logacc += weight * logf(s);
        g_inv_s = 1.f / s;
    }
}

__global__ void k_square(int src) {
    __shared__ float2 sA[16][17];
    __shared__ float2 sB[16][17];
    int i0 = blockIdx.y * 16, j0 = blockIdx.x * 16;
    int tx = threadIdx.x, ty = threadIdx.y;
    float inv = g_inv_s;
    float inv2 = inv * inv;
    const float2* S = g_G[src];
    float cr = 0.f, ci = 0.f;
    for (int k0 = 0; k0 < M_; k0 += 16) {
        int ka = k0 + tx, kb = k0 + ty;
        sA[ty][tx] = (i0 + ty < M_ && ka < M_) ? S[(i0 + ty) * M_ + ka] : make_float2(0.f, 0.f);
        sB[ty][tx] = (kb < M_ && j0 + tx < M_) ? S[kb * M_ + j0 + tx] : make_float2(0.f, 0.f);
        __syncthreads();
#pragma unroll
        for (int t = 0; t < 16; t++) {
            float2 a = sA[ty][t], b = sB[t][tx];
            cr += a.x * b.x - a.y * b.y;
            ci += a.x * b.y + a.y * b.x;
        }
        __syncthreads();
    }
    int i = i0 + ty, j = j0 + tx;
    if (i < M_ && j < M_) g_G[1 - src][i * M_ + j] = make_float2(cr * inv2, ci * inv2);
}

__global__ void k_final() {
    float st = expf(-g_logacc);
    g_step = st;
    g_thresh = LAMBDA_ * st;
}

// ---- Ahat[k',j'] = delta - step * sum_m phi[m,k']*conj(phi[m,j']) ----
__global__ void k_Ahat(const float* __restrict__ pr, const float* __restrict__ pi) {
    __shared__ float2 sK[16][17];
    __shared__ float2 sJ[16][17];
    int kr0 = blockIdx.y * 16, jc0 = blockIdx.x * 16;
    int tx = threadIdx.x, ty = threadIdx.y;
    float ar = 0.f, ai = 0.f;
    for (int m0 = 0; m0 < M_; m0 += 16) {
        int m = m0 + ty;
        int nk = kr0 + tx, nj = jc0 + tx;
        sK[ty][tx] = (m < M_ && nk < N_) ? make_float2(pr[m * N_ + nk], pi[m * N_ + nk]) : make_float2(0.f, 0.f);
        sJ[ty][tx] = (m < M_ && nj < N_) ? make_float2(pr[m * N_ + nj], pi[m * N_ + nj]) : make_float2(0.f, 0.f);
        __syncthreads();
#pragma unroll
        for (int t = 0; t < 16; t++) {
            float2 a = sK[t][ty];
            float2 b = sJ[t][tx];
            ar += a.x * b.x + a.y * b.y;   // a * conj(b)
            ai += a.y * b.x - a.x * b.y;
        }
        __syncthreads();
    }
    int kr = kr0 + ty, jc = jc0 + tx;
    if (kr < N_ && jc < N_) {
        float st = g_step;
        float2 v;
        v.x = (kr == jc ? 1.f : 0.f) - st * ar;
        v.y = -st * ai;
        g_Ahat[(size_t)kr * N_ + jc] = v;
    }
}

// ---- expand Ahat into interleaved real B^T (hi/lo bf16) ----
__global__ void k_expand() {
    size_t idx = (size_t)blockIdx.x * 256 + threadIdx.x;
    if (idx >= (size_t)NP * NP) return;
    int j = (int)(idx >> 11);      // B^T row = output col
    int k = (int)(idx & (NP - 1)); // B^T col = K index
    float val = 0.f;
    if (j < NI && k < NI) {
        int jp = j >> 1, t = j & 1, kp = k >> 1, s = k & 1;
        float2 a = g_Ahat[(size_t)kp * N_ + jp];
        val = (t == 0) ? (s == 0 ? a.x : -a.y) : (s == 0 ? a.y : a.x);
    }
    __nv_bfloat16 h = __float2bfloat16(val);
    g_Bhi[idx] = h;
    g_Blo[idx] = __float2bfloat16(val - __bfloat162float(h));
}

// ---- chat[b][2j(+1)] = step * (r conj(phi))[b,j] ----
__global__ void k_chat(const float* __restrict__ rr, const float* __restrict__ ri,
                       const float* __restrict__ pr, const float* __restrict__ pi) {
    __shared__ float2 sR[16][17];
    __shared__ float2 sF[16][17];
    int b0 = blockIdx.y * 16, j0 = blockIdx.x * 16;
    int tx = threadIdx.x, ty = threadIdx.y;
    float cr = 0.f, ci = 0.f;
    for (int m0 = 0; m0 < M_; m0 += 16) {
        int m = m0 + tx;
        sR[ty][tx] = (m < M_) ? make_float2(rr[(b0 + ty) * M_ + m], ri[(b0 + ty) * M_ + m]) : make_float2(0.f, 0.f);
        int mm = m0 + ty, j = j0 + tx;
        sF[ty][tx] = (mm < M_ && j < N_) ? make_float2(pr[mm * N_ + j], pi[mm * N_ + j]) : make_float2(0.f, 0.f);
        __syncthreads();
#pragma unroll
        for (int t = 0; t < 16; t++) {
            float2 r = sR[ty][t];
            float2 f = sF[t][tx];
            cr += r.x * f.x + r.y * f.y;   // r * conj(phi)
            ci += r.y * f.x - r.x * f.y;
        }
        __syncthreads();
    }
    int b = b0 + ty, j = j0 + tx;
    float st = g_step;
    float vr = (j < N_) ? st * cr : 0.f;
    float vi = (j < N_) ? st * ci : 0.f;
    g_chat[(size_t)b * NP + 2 * j]     = vr;
    g_chat[(size_t)b * NP + 2 * j + 1] = vi;
}

// ---------------- main iteration: w_next = shrink(w @ Bmat + chat) ------
// 128x64x64 tile, 8 warps (4x2), 3-stage cp.async ring, hi/lo 3-pass.
__global__ void __launch_bounds__(256) k_bigmma(int cur) {
    extern __shared__ char dsm[];
    const uint32_t base = smem_u32(dsm);

    const int tid = threadIdx.x;
    const int lane = tid & 31;
    const int wid = tid >> 5;
    const int warp_m = wid >> 1;   // 0..3 -> 32-row slab
    const int warp_n = wid & 1;    // 0..1 -> 32-col slab
    const int m0 = blockIdx.y * BM;
    const int n0 = blockIdx.x * BN;

    const __nv_bfloat16* __restrict__ WH = g_whi[cur];
    const __nv_bfloat16* __restrict__ WL = g_wlo[cur];
    __nv_bfloat16* __restrict__ OH = g_whi[cur ^ 1];
    __nv_bfloat16* __restrict__ OL = g_wlo[cur ^ 1];

    // loader mapping: A: 2 thr/row, 4 chunks each; B: 4 thr/row, 2 chunks each
    const int arow = tid >> 1;
    const int ac0 = (tid & 1) * 4;                     // 16B-chunk base (of 8)
    const uint32_t aS = (uint32_t)(arow * ROWB + ac0 * 16);
    const size_t aG = (size_t)(m0 + arow) * NP + ac0 * 8;
    const int brow = tid >> 2;
    const int bc0 = (tid & 3) * 2;
    const uint32_t bS = (uint32_t)(brow * ROWB + bc0 * 16);
    const size_t bG = (size_t)(n0 + brow) * NP + bc0 * 8;

#define LOAD_CHUNK(kc, st) do {                                              \
        uint32_t bb = base + (st) * STAGEB;                                  \
        size_t ko = (size_t)(kc) * BK;                                       \
        _Pragma("unroll")                                                    \
        for (int u = 0; u < 4; u++) {                                        \
            cp16(bb + aS + u * 16,         WH + aG + ko + u * 8);            \
            cp16(bb + ATILE + aS + u * 16, WL + aG + ko + u * 8);            \
        }                                                                    \
        _Pragma("unroll")                                                    \
        for (int u = 0; u < 2; u++) {                                        \
            cp16(bb + 2 * ATILE + aS * 0 + bS + u * 16,         g_Bhi + bG + ko + u * 8); \
            cp16(bb + 2 * ATILE + BTILE + bS + u * 16,          g_Blo + bG + ko + u * 8); \
        }                                                                    \
        asm volatile("cp.async.commit_group;");                              \
    } while (0)

    float acc[2][4][4] = {};

    LOAD_CHUNK(0, 0);
    LOAD_CHUNK(1, 1);

    const uint32_t aRow = (uint32_t)((warp_m * 32 + (lane & 15)) * ROWB + (lane >> 4) * 16);
    const uint32_t bRow = (uint32_t)((warp_n * 32 + (lane & 15)) * ROWB + (lane >> 4) * 16);

    for (int i = 0; i < KC; i++) {
        if (i + 1 < KC) asm volatile("cp.async.wait_group 1;");
        else            asm volatile("cp.async.wait_group 0;");
        __syncthreads();

        uint32_t bb = base + (i % 3) * STAGEB;
        uint32_t sAh = bb, sAl = bb + ATILE, sBh = bb + 2 * ATILE, sBl = bb + 2 * ATILE + BTILE;
#pragma unroll
        for (int ks = 0; ks < 4; ks++) {
            uint32_t ah[2][4], al[2][4], bh[2][4], bl[2][4];
#pragma unroll
            for (int mt = 0; mt < 2; mt++) {
                ldsm4(ah[mt], sAh + aRow + mt * (16 * ROWB) + ks * 32);
                ldsm4(al[mt], sAl + aRow + mt * (16 * ROWB) + ks * 32);
            }
#pragma unroll
            for (int ng = 0; ng < 2; ng++) {
                ldsm4(bh[ng], sBh + bRow + ng * (16 * ROWB) + ks * 32);
                ldsm4(bl[ng], sBl + bRow + ng * (16 * ROWB) + ks * 32);
            }
#pragma unroll
            for (int mt = 0; mt < 2; mt++) {
#pragma unroll
                for (int nt = 0; nt < 4; nt++) {
                    int ng = nt >> 1, hf = nt & 1;
                    mma16816(acc[mt][nt], ah[mt], bh[ng][hf], bh[ng][hf + 2]);
                    mma16816(acc[mt][nt], ah[mt], bl[ng][hf], bl[ng][hf + 2]);
                    mma16816(acc[mt][nt], al[mt], bh[ng][hf], bh[ng][hf + 2]);
                }
            }
        }
        if (i + 2 < KC) LOAD_CHUNK(i + 2, (i + 2) % 3);
    }

    // ---- epilogue: + chat, shrink, store hi/lo bf16 ----
    const float thr = g_thresh;
    const int qr = lane >> 2, qc = lane & 3;
#pragma unroll
    for (int mt = 0; mt < 2; mt++) {
        int row0 = m0 + warp_m * 32 + mt * 16 + qr;
#pragma unroll
        for (int nt = 0; nt < 4; nt++) {
            int ncol = n0 + warp_n * 32 + nt * 8 + qc * 2;
#pragma unroll
            for (int h = 0; h < 2; h++) {
                int row = row0 + h * 8;
                size_t idx = (size_t)row * NP + ncol;
                float2 ch = *reinterpret_cast<const float2*>(&g_chat[idx]);
                float re = acc[mt][nt][2 * h]     + ch.x;
                float im = acc[mt][nt][2 * h + 1] + ch.y;
                float mag = sqrtf(re * re + im * im);
                float f = (mag > thr) ? (1.f - thr / mag) : 0.f;
                re *= f; im *= f;
                __nv_bfloat16 hr = __float2bfloat16(re);
                __nv_bfloat16 hm = __float2bfloat16(im);
                __nv_bfloat162 hv; hv.x = hr; hv.y = hm;
                __nv_bfloat162 lv;
                lv.x = __float2bfloat16(re - __bfloat162float(hr));
                lv.y = __float2bfloat16(im - __bfloat162float(hm));
                *reinterpret_cast<__nv_bfloat162*>(&OH[idx]) = hv;
                *reinterpret_cast<__nv_bfloat162*>(&OL[idx]) = lv;
            }
        }
    }
}

// ---------------- output |w| -------------------------------------------
__global__ void k_absout(float* __restrict__ out) {
    int j = blockIdx.x * 256 + threadIdx.x;
    int b = blockIdx.y;
    if (j < N_) {
        size_t off = (size_t)b * NP + 2 * j;
        __nv_bfloat162 h = *reinterpret_cast<const __nv_bfloat162*>(&g_whi[0][off]);
        __nv_bfloat162 l = *reinterpret_cast<const __nv_bfloat162*>(&g_wlo[0][off]);
        float re = __bfloat162float(h.x) + __bfloat162float(l.x);
        float im = __bfloat162float(h.y) + __bfloat162float(l.y);
        out[(size_t)b * N_ + j] = sqrtf(re * re + im * im);
    }
}

// -----------------------------------------------------------------------
extern "C" void kernel_launch(void* const* d_in, const int* in_sizes, int n_in,
                              void* d_out, int out_size) {
    (void)in_sizes; (void)n_in; (void)out_size;
    const float* rr = (const float*)d_in[0];
    const float* ri = (const float*)d_in[1];
    const float* pr = (const float*)d_in[2];
    const float* pi = (const float*)d_in[3];
    float* out = (float*)d_out;

    cudaFuncSetAttribute(k_bigmma, cudaFuncAttributeMaxDynamicSharedMemorySize, SMEM_DYN);

    {
        size_t n16 = (size_t)B_ * NP * 2 / 16;
        k_zero2<<<(unsigned)((n16 + 255) / 256), 256>>>();
    }

    dim3 gG((M_ + 15) / 16, (M_ + 15) / 16), b16(16, 16);
    k_computeG<<<gG, b16>>>(pr, pi);
    float wgt = 1.f;
    for (int j = 0; j < NSQ_; j++) {
        k_trace<<<1, 512>>>(j & 1, wgt);
        k_square<<<gG, b16>>>(j & 1);
        wgt *= 0.5f;
    }
    k_trace<<<1, 512>>>(NSQ_ & 1, wgt);
    k_final<<<1, 1>>>();

    dim3 gA((N_ + 15) / 16, (N_ + 15) / 16);
    k_Ahat<<<gA, b16>>>(pr, pi);
    k_expand<<<(unsigned)(((size_t)NP * NP + 255) / 256), 256>>>();
    k_chat<<<dim3(1024 / 16, B_ / 16), b16>>>(rr, ri, pr, pi);

    dim3 gmm(NT, B_ / BM);   // 31 x 32 = 992 blocks
    for (int it = 0; it < ITERS_; it++) {
        k_bigmma<<<gmm, 256, SMEM_DYN>>>(it & 1);
    }

    k_absout<<<dim3((N_ + 255) / 256, B_), 256>>>(out);
}

// round 5
// speedup vs baseline: 1.2133x; 1.2133x over previous
#include <cuda_runtime.h>
#include <cuda_bf16.h>
#include <cstdint>
#include <math.h>

#define B_ 4096
#define M_ 306
#define N_ 984
#define LAMBDA_ 0.1f
#define ITERS_ 50
#define NSQ_ 12

#define NP 2048           // padded interleaved (re,im) storage width
#define NI 1968           // 2*N_ live columns
#define BM 64
#define BN 128
#define BK 32             // bf16 elems per K-chunk (64 bytes per row)
#define KC 62             // 62*32 = 1984 >= NI (trim dead K)

#define ROWB 80           // padded smem row stride (64B data + 16B pad)
#define ATILE (BM * ROWB)             // 5120
#define BTILE (BN * ROWB)             // 10240
#define STAGEB (2 * ATILE + 2 * BTILE)  // Ah, Al, Bh, Bl = 30720
#define SMEM_DYN (2 * STAGEB)           // 61440 -> 3 CTAs/SM

// ---------------- static device scratch (no allocations) ----------------
__device__ __nv_bfloat16 g_whi[2][(size_t)B_ * NP];
__device__ __nv_bfloat16 g_wlo[2][(size_t)B_ * NP];
__device__ __nv_bfloat16 g_Bhi[(size_t)NP * NP];   // B^T: row = out col j, col = k
__device__ __nv_bfloat16 g_Blo[(size_t)NP * NP];
__device__ float  g_chat[(size_t)B_ * NP];
__device__ float2 g_Ahat[(size_t)N_ * N_];
__device__ float2 g_G[2][M_ * M_];
__device__ float  g_logacc, g_inv_s, g_step, g_thresh;

// ---------------- PTX helpers ----------------
__device__ __forceinline__ uint32_t smem_u32(const void* p) {
    uint32_t a;
    asm("{ .reg .u64 t; cvta.to.shared.u64 t, %1; cvt.u32.u64 %0, t; }" : "=r"(a) : "l"(p));
    return a;
}
__device__ __forceinline__ void cp16(uint32_t s, const void* g) {
    asm volatile("cp.async.cg.shared.global [%0], [%1], 16;" :: "r"(s), "l"(g));
}
__device__ __forceinline__ void ldsm4(uint32_t* r, uint32_t a) {
    asm volatile("ldmatrix.sync.aligned.m8n8.x4.shared.b16 {%0,%1,%2,%3}, [%4];"
                 : "=r"(r[0]), "=r"(r[1]), "=r"(r[2]), "=r"(r[3]) : "r"(a));
}
__device__ __forceinline__ void mma16816(float* c, const uint32_t* a, uint32_t b0, uint32_t b1) {
    asm volatile(
        "mma.sync.aligned.m16n8k16.row.col.f32.bf16.bf16.f32 "
        "{%0,%1,%2,%3}, {%4,%5,%6,%7}, {%8,%9}, {%0,%1,%2,%3};"
        : "+f"(c[0]), "+f"(c[1]), "+f"(c[2]), "+f"(c[3])
        : "r"(a[0]), "r"(a[1]), "r"(a[2]), "r"(a[3]), "r"(b0), "r"(b1));
}

// ---------------- setup: zero W buffer 0 + logacc ----------------
__global__ void k_zero2() {
    size_t i = (size_t)blockIdx.x * blockDim.x + threadIdx.x;
    size_t n16 = (size_t)B_ * NP * 2 / 16;
    if (i < n16) {
        reinterpret_cast<uint4*>(g_whi[0])[i] = make_uint4(0, 0, 0, 0);
        reinterpret_cast<uint4*>(g_wlo[0])[i] = make_uint4(0, 0, 0, 0);
    }
    if (i == 0) g_logacc = 0.f;
}

// ---------------- spectral norm via Gram + trace-normalized squaring ----
__global__ void k_computeG(const float* __restrict__ pr, const float* __restrict__ pi) {
    __shared__ float2 sA[16][17];
    __shared__ float2 sB[16][17];
    int i0 = blockIdx.y * 16, j0 = blockIdx.x * 16;
    int tx = threadIdx.x, ty = threadIdx.y;
    float cr = 0.f, ci = 0.f;
    for (int n0 = 0; n0 < N_; n0 += 16) {
        int ac = n0 + tx, ar = i0 + ty, br = j0 + ty;
        sA[ty][tx] = (ar < M_ && ac < N_) ? make_float2(pr[ar * N_ + ac], pi[ar * N_ + ac]) : make_float2(0.f, 0.f);
        sB[ty][tx] = (br < M_ && ac < N_) ? make_float2(pr[br * N_ + ac], pi[br * N_ + ac]) : make_float2(0.f, 0.f);
        __syncthreads();
#pragma unroll
        for (int t = 0; t < 16; t++) {
            float2 a = sA[ty][t], b = sB[tx][t];
            cr += a.x * b.x + a.y * b.y;
            ci += a.y * b.x - a.x * b.y;
        }
        __syncthreads();
    }
    int i = i0 + ty, j = j0 + tx;
    if (i < M_ && j < M_) g_G[0][i * M_ + j] = make_float2(cr, ci);
}

__global__ void k_trace(int src, float weight) {
    __shared__ float red[512];
    int t = threadIdx.x;
    red[t] = (t < M_) ? g_G[src][t * (M_ + 1)].x : 0.f;
    __syncthreads();
    for (int s = 256; s > 0; s >>= 1) {
        if (t < s) red[t] += red[t + s];
        __syncthreads();
    }
    if (t == 0) {
        float s = red[0];
        g_logacc += weight * logf(s);
        g_inv_s = 1.f / s;
    }
}

__global__ void k_square(int src) {
    __shared__ float2 sA[16][17];
    __shared__ float2 sB[16][17];
    int i0 = blockIdx.y * 16, j0 = blockIdx.x * 16;
    int tx = threadIdx.x, ty = threadIdx.y;
    float inv = g_inv_s;
    float inv2 = inv * inv;
    const float2* S = g_G[src];
    float cr = 0.f, ci = 0.f;
    for (int k0 = 0; k0 < M_; k0 += 16) {
        int ka = k0 + tx, kb = k0 + ty;
        sA[ty][tx] = (i0 + ty < M_ && ka < M_) ? S[(i0 + ty) * M_ + ka] : make_float2(0.f, 0.f);
        sB[ty][tx] = (kb < M_ && j0 + tx < M_) ? S[kb * M_ + j0 + tx] : make_float2(0.f, 0.f);
        __syncthreads();
#pragma unroll
        for (int t = 0; t < 16; t++) {
            float2 a = sA[ty][t], b = sB[t][tx];
            cr += a.x * b.x - a.y * b.y;
            ci += a.x * b.y + a.y * b.x;
        }
        __syncthreads();
    }
    int i = i0 + ty, j = j0 + tx;
    if (i < M_ && j < M_) g_G[1 - src][i * M_ + j] = make_float2(cr * inv2, ci * inv2);
}

__global__ void k_final() {
    float st = expf(-g_logacc);
    g_step = st;
    g_thresh = LAMBDA_ * st;
}

// ---- Ahat[k',j'] = delta - step * sum_m phi[m,k']*conj(phi[m,j']) ----
__global__ void k_Ahat(const float* __restrict__ pr, const float* __restrict__ pi) {
    __shared__ float2 sK[16][17];
    __shared__ float2 sJ[16][17];
    int kr0 = blockIdx.y * 16, jc0 = blockIdx.x * 16;
    int tx = threadIdx.x, ty = threadIdx.y;
    float ar = 0.f, ai = 0.f;
    for (int m0 = 0; m0 < M_; m0 += 16) {
        int m = m0 + ty;
        int nk = kr0 + tx, nj = jc0 + tx;
        sK[ty][tx] = (m < M_ && nk < N_) ? make_float2(pr[m * N_ + nk], pi[m * N_ + nk]) : make_float2(0.f, 0.f);
        sJ[ty][tx] = (m < M_ && nj < N_) ? make_float2(pr[m * N_ + nj], pi[m * N_ + nj]) : make_float2(0.f, 0.f);
        __syncthreads();
#pragma unroll
        for (int t = 0; t < 16; t++) {
            float2 a = sK[t][ty];
            float2 b = sJ[t][tx];
            ar += a.x * b.x + a.y * b.y;   // a * conj(b)
            ai += a.y * b.x - a.x * b.y;
        }
        __syncthreads();
    }
    int kr = kr0 + ty, jc = jc0 + tx;
    if (kr < N_ && jc < N_) {
        float st = g_step;
        float2 v;
        v.x = (kr == jc ? 1.f : 0.f) - st * ar;
        v.y = -st * ai;
        g_Ahat[(size_t)kr * N_ + jc] = v;
    }
}

// ---- expand Ahat into interleaved real B^T (hi/lo bf16) ----
__global__ void k_expand() {
    size_t idx = (size_t)blockIdx.x * 256 + threadIdx.x;
    if (idx >= (size_t)NP * NP) return;
    int j = (int)(idx >> 11);      // B^T row = output col
    int k = (int)(idx & (NP - 1)); // B^T col = K index
    float val = 0.f;
    if (j < NI && k < NI) {
        int jp = j >> 1, t = j & 1, kp = k >> 1, s = k & 1;
        float2 a = g_Ahat[(size_t)kp * N_ + jp];
        val = (t == 0) ? (s == 0 ? a.x : -a.y) : (s == 0 ? a.y : a.x);
    }
    __nv_bfloat16 h = __float2bfloat16(val);
    g_Bhi[idx] = h;
    g_Blo[idx] = __float2bfloat16(val - __bfloat162float(h));
}

// ---- chat[b][2j(+1)] = step * (r conj(phi))[b,j] ----
__global__ void k_chat(const float* __restrict__ rr, const float* __restrict__ ri,
                       const float* __restrict__ pr, const float* __restrict__ pi) {
    __shared__ float2 sR[16][17];
    __shared__ float2 sF[16][17];
    int b0 = blockIdx.y * 16, j0 = blockIdx.x * 16;
    int tx = threadIdx.x, ty = threadIdx.y;
    float cr = 0.f, ci = 0.f;
    for (int m0 = 0; m0 < M_; m0 += 16) {
        int m = m0 + tx;
        sR[ty][tx] = (m < M_) ? make_float2(rr[(b0 + ty) * M_ + m], ri[(b0 + ty) * M_ + m]) : make_float2(0.f, 0.f);
        int mm = m0 + ty, j = j0 + tx;
        sF[ty][tx] = (mm < M_ && j < N_) ? make_float2(pr[mm * N_ + j], pi[mm * N_ + j]) : make_float2(0.f, 0.f);
        __syncthreads();
#pragma unroll
        for (int t = 0; t < 16; t++) {
            float2 r = sR[ty][t];
            float2 f = sF[t][tx];
            cr += r.x * f.x + r.y * f.y;   // r * conj(phi)
            ci += r.y * f.x - r.x * f.y;
        }
        __syncthreads();
    }
    int b = b0 + ty, j = j0 + tx;
    float st = g_step;
    float vr = (j < N_) ? st * cr : 0.f;
    float vi = (j < N_) ? st * ci : 0.f;
    g_chat[(size_t)b * NP + 2 * j]     = vr;
    g_chat[(size_t)b * NP + 2 * j + 1] = vi;
}

// ---------------- main iteration: w_next = shrink(w @ Bmat + chat) ------
// 64x128x32 tile, 8 warps (2x4), 2-stage cp.async, hi/lo 3-pass.
__global__ void __launch_bounds__(256) k_bigmma(int cur) {
    extern __shared__ char dsm[];
    const uint32_t base = smem_u32(dsm);

    const int tid = threadIdx.x;
    const int lane = tid & 31;
    const int wid = tid >> 5;
    const int warp_m = wid & 1;    // 0..1 -> 32-row slab
    const int warp_n = wid >> 1;   // 0..3 -> 32-col slab
    const int m0 = blockIdx.y * BM;
    const int n0 = blockIdx.x * BN;

    const __nv_bfloat16* __restrict__ WH = g_whi[cur];
    const __nv_bfloat16* __restrict__ WL = g_wlo[cur];
    __nv_bfloat16* __restrict__ OH = g_whi[cur ^ 1];
    __nv_bfloat16* __restrict__ OL = g_wlo[cur ^ 1];

    // loaders: A tile 64 rows x 64B -> 4 thr/row, 1 chunk each
    const int arow = tid >> 2;
    const int ac = tid & 3;
    const uint32_t aS = (uint32_t)(arow * ROWB + ac * 16);
    const size_t aG = (size_t)(m0 + arow) * NP + ac * 8;
    // B tile 128 rows x 64B -> 2 thr/row, 2 chunks each
    const int brow = tid >> 1;
    const int bc = (tid & 1) * 2;
    const uint32_t bS = (uint32_t)(brow * ROWB + bc * 16);
    const size_t bG = (size_t)(n0 + brow) * NP + bc * 8;

    float acc[2][4][4] = {};

    // prologue: chunk 0 -> stage 0
    {
        uint32_t bb = base;
        cp16(bb + aS,                     WH + aG);
        cp16(bb + ATILE + aS,             WL + aG);
        cp16(bb + 2 * ATILE + bS,         g_Bhi + bG);
        cp16(bb + 2 * ATILE + bS + 16,    g_Bhi + bG + 8);
        cp16(bb + 2 * ATILE + BTILE + bS,      g_Blo + bG);
        cp16(bb + 2 * ATILE + BTILE + bS + 16, g_Blo + bG + 8);
        asm volatile("cp.async.commit_group;");
    }

    const uint32_t aRow = (uint32_t)((warp_m * 32 + (lane & 15)) * ROWB + (lane >> 4) * 16);
    const uint32_t bRow = (uint32_t)((warp_n * 32 + (lane & 15)) * ROWB + (lane >> 4) * 16);

    for (int i = 0; i < KC; i++) {
        if (i + 1 < KC) {
            uint32_t bb = base + ((i + 1) & 1) * STAGEB;
            size_t ko = (size_t)(i + 1) * BK;
            cp16(bb + aS,                     WH + aG + ko);
            cp16(bb + ATILE + aS,             WL + aG + ko);
            cp16(bb + 2 * ATILE + bS,         g_Bhi + bG + ko);
            cp16(bb + 2 * ATILE + bS + 16,    g_Bhi + bG + ko + 8);
            cp16(bb + 2 * ATILE + BTILE + bS,      g_Blo + bG + ko);
            cp16(bb + 2 * ATILE + BTILE + bS + 16, g_Blo + bG + ko + 8);
            asm volatile("cp.async.commit_group;");
            asm volatile("cp.async.wait_group 1;");
        } else {
            asm volatile("cp.async.wait_group 0;");
        }
        __syncthreads();

        uint32_t bb = base + (i & 1) * STAGEB;
        uint32_t sAh = bb, sAl = bb + ATILE, sBh = bb + 2 * ATILE, sBl = bb + 2 * ATILE + BTILE;
#pragma unroll
        for (int ks = 0; ks < 2; ks++) {
            uint32_t ah[2][4], al[2][4], bh[2][4], bl[2][4];
#pragma unroll
            for (int mt = 0; mt < 2; mt++) {
                ldsm4(ah[mt], sAh + aRow + mt * (16 * ROWB) + ks * 32);
                ldsm4(al[mt], sAl + aRow + mt * (16 * ROWB) + ks * 32);
            }
#pragma unroll
            for (int ng = 0; ng < 2; ng++) {
                ldsm4(bh[ng], sBh + bRow + ng * (16 * ROWB) + ks * 32);
                ldsm4(bl[ng], sBl + bRow + ng * (16 * ROWB) + ks * 32);
            }
#pragma unroll
            for (int mt = 0; mt < 2; mt++) {
#pragma unroll
                for (int nt = 0; nt < 4; nt++) {
                    int ng = nt >> 1, hf = nt & 1;
                    mma16816(acc[mt][nt], ah[mt], bh[ng][hf], bh[ng][hf + 2]);
                    mma16816(acc[mt][nt], ah[mt], bl[ng][hf], bl[ng][hf + 2]);
                    mma16816(acc[mt][nt], al[mt], bh[ng][hf], bh[ng][hf + 2]);
                }
            }
        }
        __syncthreads();
    }

    // ---- epilogue: + chat, shrink, store hi/lo bf16 ----
    const float thr = g_thresh;
    const int qr = lane >> 2, qc = lane & 3;
#pragma unroll
    for (int mt = 0; mt < 2; mt++) {
        int row0 = m0 + warp_m * 32 + mt * 16 + qr;
#pragma unroll
        for (int nt = 0; nt < 4; nt++) {
            int ncol = n0 + warp_n * 32 + nt * 8 + qc * 2;
#pragma unroll
            for (int h = 0; h < 2; h++) {
                int row = row0 + h * 8;
                size_t idx = (size_t)row * NP + ncol;
                float2 ch = *reinterpret_cast<const float2*>(&g_chat[idx]);
                float re = acc[mt][nt][2 * h]     + ch.x;
                float im = acc[mt][nt][2 * h + 1] + ch.y;
                float mag = sqrtf(re * re + im * im);
                float f = (mag > thr) ? (1.f - thr / mag) : 0.f;
                re *= f; im *= f;
                __nv_bfloat16 hr = __float2bfloat16(re);
                __nv_bfloat16 hm = __float2bfloat16(im);
                __nv_bfloat162 hv; hv.x = hr; hv.y = hm;
                __nv_bfloat162 lv;
                lv.x = __float2bfloat16(re - __bfloat162float(hr));
                lv.y = __float2bfloat16(im - __bfloat162float(hm));
                *reinterpret_cast<__nv_bfloat162*>(&OH[idx]) = hv;
                *reinterpret_cast<__nv_bfloat162*>(&OL[idx]) = lv;
            }
        }
    }
}

// ---------------- output |w| -------------------------------------------
__global__ void k_absout(float* __restrict__ out) {
    int j = blockIdx.x * 256 + threadIdx.x;
    int b = blockIdx.y;
    if (j < N_) {
        size_t off = (size_t)b * NP + 2 * j;
        __nv_bfloat162 h = *reinterpret_cast<const __nv_bfloat162*>(&g_whi[0][off]);
        __nv_bfloat162 l = *reinterpret_cast<const __nv_bfloat162*>(&g_wlo[0][off]);
        float re = __bfloat162float(h.x) + __bfloat162float(l.x);
        float im = __bfloat162float(h.y) + __bfloat162float(l.y);
        out[(size_t)b * N_ + j] = sqrtf(re * re + im * im);
    }
}

// -----------------------------------------------------------------------
extern "C" void kernel_launch(void* const* d_in, const int* in_sizes, int n_in,
                              void* d_out, int out_size) {
    (void)in_sizes; (void)n_in; (void)out_size;
    const float* rr = (const float*)d_in[0];
    const float* ri = (const float*)d_in[1];
    const float* pr = (const float*)d_in[2];
    const float* pi = (const float*)d_in[3];
    float* out = (float*)d_out;

    cudaFuncSetAttribute(k_bigmma, cudaFuncAttributeMaxDynamicSharedMemorySize, SMEM_DYN);

    {
        size_t n16 = (size_t)B_ * NP * 2 / 16;
        k_zero2<<<(unsigned)((n16 + 255) / 256), 256>>>();
    }

    dim3 gG((M_ + 15) / 16, (M_ + 15) / 16), b16(16, 16);
    k_computeG<<<gG, b16>>>(pr, pi);
    float wgt = 1.f;
    for (int j = 0; j < NSQ_; j++) {
        k_trace<<<1, 512>>>(j & 1, wgt);
        k_square<<<gG, b16>>>(j & 1);
        wgt *= 0.5f;
    }
    k_trace<<<1, 512>>>(NSQ_ & 1, wgt);
    k_final<<<1, 1>>>();

    dim3 gA((N_ + 15) / 16, (N_ + 15) / 16);
    k_Ahat<<<gA, b16>>>(pr, pi);
    k_expand<<<(unsigned)(((size_t)NP * NP + 255) / 256), 256>>>();
    k_chat<<<dim3(1024 / 16, B_ / 16), b16>>>(rr, ri, pr, pi);

    dim3 gmm(NP / BN, B_ / BM);   // 16 x 64 = 1024 blocks
    for (int it = 0; it < ITERS_; it++) {
        k_bigmma<<<gmm, 256, SMEM_DYN>>>(it & 1);
    }

    k_absout<<<dim3((N_ + 255) / 256, B_), 256>>>(out);
}